// round 3
// baseline (speedup 1.0000x reference)
#include <cuda_runtime.h>
#include <cuda_bf16.h>

#define THREADS 256
#define ITEMS   16   // nnz per thread; 16 keeps int4/float4 vector loads + high MLP

__global__ void init_out_kernel(float* __restrict__ y,
                                const float* __restrict__ bias, int n) {
    int i = blockIdx.x * blockDim.x + threadIdx.x;
    if (i < n) y[i] = bias[i];
}

__global__ __launch_bounds__(THREADS)
void spmv_coo_kernel(const float* __restrict__ vals,
                     const float* __restrict__ x,
                     const int*   __restrict__ rows,
                     const int*   __restrict__ cols,
                     float*       __restrict__ y,
                     long long nnz) {
    long long tid  = (long long)blockIdx.x * blockDim.x + threadIdx.x;
    long long base = tid * ITEMS;
    if (base >= nnz) return;

    int   r[ITEMS];
    int   c[ITEMS];
    float v[ITEMS];

    if (base + ITEMS <= nnz) {
        // Fast path: fully in-range chunk, vectorized 16B loads (front-batched -> high MLP)
        const int4*   rp = reinterpret_cast<const int4*>(rows + base);
        const int4*   cp = reinterpret_cast<const int4*>(cols + base);
        const float4* vp = reinterpret_cast<const float4*>(vals + base);
        #pragma unroll
        for (int i = 0; i < ITEMS / 4; i++) {
            int4   rr = __ldg(&rp[i]);
            int4   cc = __ldg(&cp[i]);
            float4 vv = __ldg(&vp[i]);
            r[4*i+0] = rr.x; r[4*i+1] = rr.y; r[4*i+2] = rr.z; r[4*i+3] = rr.w;
            c[4*i+0] = cc.x; c[4*i+1] = cc.y; c[4*i+2] = cc.z; c[4*i+3] = cc.w;
            v[4*i+0] = vv.x; v[4*i+1] = vv.y; v[4*i+2] = vv.z; v[4*i+3] = vv.w;
        }

        // Gather x (random 4B loads; 800KB table -> L2 resident). Issue all 16
        // before consuming so the L2 latency overlaps.
        float xv[ITEMS];
        #pragma unroll
        for (int i = 0; i < ITEMS; i++) xv[i] = __ldg(&x[c[i]]);

        // Sequential segment scan over the sorted-row chunk.
        float acc = 0.0f;
        int   cur = r[0];
        #pragma unroll
        for (int i = 0; i < ITEMS; i++) {
            if (r[i] != cur) {
                atomicAdd(&y[cur], acc);
                acc = 0.0f;
                cur = r[i];
            }
            acc = fmaf(v[i], xv[i], acc);
        }
        atomicAdd(&y[cur], acc);
    } else {
        // Tail chunk: scalar, bounds-checked
        int count = (int)(nnz - base);
        float acc = 0.0f;
        int   cur = rows[base];
        for (int i = 0; i < count; i++) {
            int   ri = rows[base + i];
            int   ci = cols[base + i];
            float vi = vals[base + i];
            if (ri != cur) {
                atomicAdd(&y[cur], acc);
                acc = 0.0f;
                cur = ri;
            }
            acc = fmaf(vi, __ldg(&x[ci]), acc);
        }
        atomicAdd(&y[cur], acc);
    }
}

extern "C" void kernel_launch(void* const* d_in, const int* in_sizes, int n_in,
                              void* d_out, int out_size) {
    // metadata order: vals[NNZ] f32, x[N_COLS] f32, bias[N_ROWS] f32,
    //                 rows[NNZ] i32, cols[NNZ] i32, n_rows (ignored)
    const float* vals = (const float*)d_in[0];
    const float* x    = (const float*)d_in[1];
    const float* bias = (const float*)d_in[2];
    const int*   rows = (const int*)d_in[3];
    const int*   cols = (const int*)d_in[4];
    float* y = (float*)d_out;

    long long nnz = in_sizes[0];
    int n_rows    = in_sizes[2];

    // 1) y = bias  (d_out is poisoned before timing)
    {
        int grid = (n_rows + THREADS - 1) / THREADS;
        init_out_kernel<<<grid, THREADS>>>(y, bias, n_rows);
    }

    // 2) y += segment_sum(vals * x[cols])
    {
        long long chunks = (nnz + ITEMS - 1) / ITEMS;
        int grid = (int)((chunks + THREADS - 1) / THREADS);
        spmv_coo_kernel<<<grid, THREADS>>>(vals, x, rows, cols, y, nnz);
    }
}

// round 4
// speedup vs baseline: 1.6276x; 1.6276x over previous
#include <cuda_runtime.h>
#include <cuda_bf16.h>

#define THREADS 256
#define ITEMS   8    // nnz per thread; smaller chunk -> fewer regs -> higher occupancy

__global__ void init_out_kernel(float* __restrict__ y,
                                const float* __restrict__ bias, int n) {
    int i = blockIdx.x * blockDim.x + threadIdx.x;
    if (i < n) y[i] = bias[i];
}

__global__ __launch_bounds__(THREADS, 6)
void spmv_coo_kernel(const float* __restrict__ vals,
                     const float* __restrict__ x,
                     const int*   __restrict__ rows,
                     const int*   __restrict__ cols,
                     float*       __restrict__ y,
                     long long nnz) {
    long long tid  = (long long)blockIdx.x * blockDim.x + threadIdx.x;
    long long base = tid * ITEMS;
    if (base >= nnz) return;

    if (base + ITEMS <= nnz) {
        // Streaming loads: 2x int4 rows, 2x int4 cols, 2x float4 vals (front-batched)
        const int4*   rp = reinterpret_cast<const int4*>(rows + base);
        const int4*   cp = reinterpret_cast<const int4*>(cols + base);
        const float4* vp = reinterpret_cast<const float4*>(vals + base);

        int4   r0 = __ldg(&rp[0]);
        int4   r1 = __ldg(&rp[1]);
        int4   c0 = __ldg(&cp[0]);
        int4   c1 = __ldg(&cp[1]);
        float4 v0 = __ldg(&vp[0]);
        float4 v1 = __ldg(&vp[1]);

        int r[ITEMS] = {r0.x, r0.y, r0.z, r0.w, r1.x, r1.y, r1.z, r1.w};
        float v[ITEMS] = {v0.x, v0.y, v0.z, v0.w, v1.x, v1.y, v1.z, v1.w};

        // Gather x: 8 independent random 4B loads, all issued before any use
        // so L2 latency overlaps across the batch and across warps.
        float xv[ITEMS];
        xv[0] = __ldg(&x[c0.x]);
        xv[1] = __ldg(&x[c0.y]);
        xv[2] = __ldg(&x[c0.z]);
        xv[3] = __ldg(&x[c0.w]);
        xv[4] = __ldg(&x[c1.x]);
        xv[5] = __ldg(&x[c1.y]);
        xv[6] = __ldg(&x[c1.z]);
        xv[7] = __ldg(&x[c1.w]);

        // Sequential segment scan over the sorted-row chunk.
        float acc = 0.0f;
        int   cur = r[0];
        #pragma unroll
        for (int i = 0; i < ITEMS; i++) {
            if (r[i] != cur) {
                atomicAdd(&y[cur], acc);
                acc = 0.0f;
                cur = r[i];
            }
            acc = fmaf(v[i], xv[i], acc);
        }
        atomicAdd(&y[cur], acc);
    } else {
        // Tail chunk: scalar, bounds-checked (unused when nnz % ITEMS == 0)
        int count = (int)(nnz - base);
        float acc = 0.0f;
        int   cur = rows[base];
        for (int i = 0; i < count; i++) {
            int   ri = rows[base + i];
            int   ci = cols[base + i];
            float vi = vals[base + i];
            if (ri != cur) {
                atomicAdd(&y[cur], acc);
                acc = 0.0f;
                cur = ri;
            }
            acc = fmaf(vi, __ldg(&x[ci]), acc);
        }
        atomicAdd(&y[cur], acc);
    }
}

extern "C" void kernel_launch(void* const* d_in, const int* in_sizes, int n_in,
                              void* d_out, int out_size) {
    // metadata order: vals[NNZ] f32, x[N_COLS] f32, bias[N_ROWS] f32,
    //                 rows[NNZ] i32, cols[NNZ] i32, n_rows (ignored)
    const float* vals = (const float*)d_in[0];
    const float* x    = (const float*)d_in[1];
    const float* bias = (const float*)d_in[2];
    const int*   rows = (const int*)d_in[3];
    const int*   cols = (const int*)d_in[4];
    float* y = (float*)d_out;

    long long nnz = in_sizes[0];
    int n_rows    = in_sizes[2];

    // 1) y = bias  (d_out is poisoned before timing)
    {
        int grid = (n_rows + THREADS - 1) / THREADS;
        init_out_kernel<<<grid, THREADS>>>(y, bias, n_rows);
    }

    // 2) y += segment_sum(vals * x[cols])
    {
        long long chunks = (nnz + ITEMS - 1) / ITEMS;
        int grid = (int)((chunks + THREADS - 1) / THREADS);
        spmv_coo_kernel<<<grid, THREADS>>>(vals, x, rows, cols, y, nnz);
    }
}

// round 6
// speedup vs baseline: 1.7349x; 1.0660x over previous
#include <cuda_runtime.h>
#include <cuda_bf16.h>

#define THREADS  256
#define ITEMS    8
#define FULLMASK 0xffffffffu

__global__ void init_out_kernel(float* __restrict__ y,
                                const float* __restrict__ bias, int n) {
    int i = blockIdx.x * blockDim.x + threadIdx.x;
    if (i < n) y[i] = bias[i];
}

__global__ __launch_bounds__(THREADS, 6)
void spmv_coo_kernel(const float* __restrict__ vals,
                     const float* __restrict__ x,
                     const int*   __restrict__ rows,
                     const int*   __restrict__ cols,
                     float*       __restrict__ y,
                     long long nnz) {
    long long tid  = (long long)blockIdx.x * blockDim.x + threadIdx.x;
    long long base = tid * ITEMS;
    int lane = threadIdx.x & 31;
    // First nnz index of this warp's 32-chunk span (warp-uniform).
    long long warpBase = (tid - lane) * (long long)ITEMS;
    bool warpFull = (warpBase + 32LL * ITEMS) <= nnz;   // warp-uniform predicate

    if (warpFull) {
        // ---- Streaming loads: evict-first (__ldcs) so x keeps L1 residency ----
        const int4*   rp = reinterpret_cast<const int4*>(rows + base);
        const int4*   cp = reinterpret_cast<const int4*>(cols + base);
        const float4* vp = reinterpret_cast<const float4*>(vals + base);

        int4   c0 = __ldcs(&cp[0]);
        int4   c1 = __ldcs(&cp[1]);
        int4   r0 = __ldcs(&rp[0]);
        int4   r1 = __ldcs(&rp[1]);
        float4 v0 = __ldcs(&vp[0]);
        float4 v1 = __ldcs(&vp[1]);

        // ---- Gather x: 8 independent random 4B loads, default caching (L1) ----
        float xv[ITEMS];
        xv[0] = __ldg(&x[c0.x]);
        xv[1] = __ldg(&x[c0.y]);
        xv[2] = __ldg(&x[c0.z]);
        xv[3] = __ldg(&x[c0.w]);
        xv[4] = __ldg(&x[c1.x]);
        xv[5] = __ldg(&x[c1.y]);
        xv[6] = __ldg(&x[c1.z]);
        xv[7] = __ldg(&x[c1.w]);

        int   r[ITEMS] = {r0.x, r0.y, r0.z, r0.w, r1.x, r1.y, r1.z, r1.w};
        float v[ITEMS] = {v0.x, v0.y, v0.z, v0.w, v1.x, v1.y, v1.z, v1.w};

        // ---- Per-thread segment scan; capture head segment, flush interiors ----
        float acc = 0.0f;
        int   cur = r[0];
        float headAcc = 0.0f;
        int   headRow = 0;
        bool  closed  = false;   // chunk contains >=1 row boundary
        #pragma unroll
        for (int i = 0; i < ITEMS; i++) {
            if (r[i] != cur) {
                if (!closed) { headRow = cur; headAcc = acc; closed = true; }
                else         { atomicAdd(&y[cur], acc); }   // interior segment (rare)
                acc = 0.0f;
                cur = r[i];
            }
            acc = fmaf(v[i], xv[i], acc);
        }
        // Head segment may continue the previous lane's tail row; flushing it
        // separately is still correct (y accumulates via atomics).
        if (closed) atomicAdd(&y[headRow], headAcc);

        // ---- Warp segmented inclusive scan over tail accumulators ----
        // Rows sorted => lanes sharing the same tail row are contiguous.
        int lrprev = __shfl_up_sync(FULLMASK, cur, 1);
        unsigned headf = (lane == 0) || (cur != lrprev);

        float    vsum = acc;
        unsigned stop = headf;
        #pragma unroll
        for (int d = 1; d < 32; d <<= 1) {
            float    pv = __shfl_up_sync(FULLMASK, vsum, d);
            unsigned ps = __shfl_up_sync(FULLMASK, stop, d);
            if (lane >= d && !stop) { vsum += pv; stop = ps; }
        }
        // Run-end lane emits ONE atomic for the whole run.
        unsigned hnext = __shfl_down_sync(FULLMASK, headf, 1);
        if (lane == 31 || hnext) atomicAdd(&y[cur], vsum);
    } else {
        // ---- Tail warp: scalar, bounds-checked, no warp collectives ----
        if (base >= nnz) return;
        long long end = base + ITEMS;
        if (end > nnz) end = nnz;
        float acc = 0.0f;
        int   cur = rows[base];
        for (long long i = base; i < end; i++) {
            int   ri = rows[i];
            int   ci = cols[i];
            float vi = vals[i];
            if (ri != cur) {
                atomicAdd(&y[cur], acc);
                acc = 0.0f;
                cur = ri;
            }
            acc = fmaf(vi, __ldg(&x[ci]), acc);
        }
        atomicAdd(&y[cur], acc);
    }
}

extern "C" void kernel_launch(void* const* d_in, const int* in_sizes, int n_in,
                              void* d_out, int out_size) {
    // metadata order: vals[NNZ] f32, x[N_COLS] f32, bias[N_ROWS] f32,
    //                 rows[NNZ] i32, cols[NNZ] i32, n_rows (ignored)
    const float* vals = (const float*)d_in[0];
    const float* x    = (const float*)d_in[1];
    const float* bias = (const float*)d_in[2];
    const int*   rows = (const int*)d_in[3];
    const int*   cols = (const int*)d_in[4];
    float* y = (float*)d_out;

    long long nnz = in_sizes[0];
    int n_rows    = in_sizes[2];

    // 1) y = bias  (d_out is poisoned before timing)
    {
        int grid = (n_rows + THREADS - 1) / THREADS;
        init_out_kernel<<<grid, THREADS>>>(y, bias, n_rows);
    }

    // 2) y += segment_sum(vals * x[cols])
    {
        long long chunks = (nnz + ITEMS - 1) / ITEMS;
        int grid = (int)((chunks + THREADS - 1) / THREADS);
        spmv_coo_kernel<<<grid, THREADS>>>(vals, x, rows, cols, y, nnz);
    }
}